// round 5
// baseline (speedup 1.0000x reference)
#include <cuda_runtime.h>
#include <cstdint>

// Problem shape (fixed): input1/2 [4,3,720,1280] f32, flow3/4 [4,2,720,1280] f32
namespace {
constexpr int Wd  = 1280;
constexpr int Hd  = 720;
constexpr int Bd  = 4;
constexpr int HW  = Hd * Wd;
constexpr int BHW = Bd * HW;

constexpr float INV_LE  = 255.0f / 30.0f;              // 1 / LAMBDA_E
constexpr float INV2S2  = 1.0f / (2.0f * 1.5f * 1.5f); // 1/(2*sigma_d^2)
constexpr float THRESH_ = 1e-6f;
constexpr float EPS_    = 1e-6f;

constexpr int EX = 32, EY = 16;   // errfw tile (512 threads)
constexpr int TX = 32, TY = 8;    // splat tile (256 threads)
constexpr int HLO = 8;            // splat smem halo (covers |flow| < 7)
constexpr int SWW = TX + 2 * HLO; // 48
constexpr int SWH = TY + 2 * HLO; // 24
}

// Scratch: branch-indexed. acc4 = (p_r, p_g, p_b, pw), accR = rw.
__device__ float  g_fw   [2][BHW];
__device__ float4 g_acc4 [2][BHW];
__device__ float4 g_accR4[2][BHW / 4];

// ---------------------------------------------------------------------------
// Fused: photometric error (bilinear warp) + 3x3 box + fw = exp(-(e/le)^2),
// plus zeroing of this pixel's splat accumulators. grid.z = b + 4*br.
// ---------------------------------------------------------------------------
__device__ __forceinline__ float photo_err(
    const float* __restrict__ i1, const float* __restrict__ i2,
    const float* __restrict__ flow, int b, int x, int y)
{
    int r = y * Wd + x;
    float u = __ldg(flow + b * 2 * HW + r);
    float v = __ldg(flow + b * 2 * HW + HW + r);

    float gx = fminf(fmaxf((float)x + u, 0.f), (float)(Wd - 1));
    float gy = fminf(fmaxf((float)y + v, 0.f), (float)(Hd - 1));
    float x0f = floorf(gx), y0f = floorf(gy);
    int x0 = (int)x0f, y0 = (int)y0f;
    int x1 = min(x0 + 1, Wd - 1), y1 = min(y0 + 1, Hd - 1);
    float wx = gx - x0f, wy = gy - y0f;
    float w00 = (1.f - wx) * (1.f - wy);
    float w01 = wx * (1.f - wy);
    float w10 = (1.f - wx) * wy;
    float w11 = wx * wy;

    const float* i2b = i2 + b * 3 * HW;
    const float* i1b = i1 + b * 3 * HW;
    float e = 0.f;
#pragma unroll
    for (int c = 0; c < 3; c++) {
        const float* ip = i2b + c * HW;
        float wv = __ldg(ip + y0 * Wd + x0) * w00 + __ldg(ip + y0 * Wd + x1) * w01
                 + __ldg(ip + y1 * Wd + x0) * w10 + __ldg(ip + y1 * Wd + x1) * w11;
        e += fabsf(__ldg(i1b + c * HW + r) - wv);
    }
    return e * (1.f / 3.f);
}

__global__ void __launch_bounds__(EX * EY) k_errfw(
    const float* __restrict__ in1, const float* __restrict__ in2,
    const float* __restrict__ fl1, const float* __restrict__ fl2)
{
    __shared__ float serr[EY + 2][EX + 2];

    int br = blockIdx.z >> 2;
    int b  = blockIdx.z & 3;
    const float* i1   = br ? in2 : in1;
    const float* i2   = br ? in1 : in2;
    const float* flow = br ? fl2 : fl1;

    int bx = blockIdx.x * EX;
    int by = blockIdx.y * EY;
    int t  = threadIdx.y * EX + threadIdx.x;

    for (int idx = t; idx < (EY + 2) * (EX + 2); idx += EX * EY) {
        int j = idx / (EX + 2);
        int i = idx - j * (EX + 2);
        int ex = bx + i - 1;
        int ey = by + j - 1;
        float e = 0.f;
        if ((unsigned)ex < (unsigned)Wd && (unsigned)ey < (unsigned)Hd)
            e = photo_err(i1, i2, flow, b, ex, ey);
        serr[j][i] = e;
    }
    __syncthreads();

    int lx = threadIdx.x, ly = threadIdx.y;
    float s = 0.f;
#pragma unroll
    for (int j = 0; j < 3; j++)
#pragma unroll
        for (int i = 0; i < 3; i++)
            s += serr[ly + j][lx + i];

    float tt = s * (1.f / 9.f) * INV_LE;
    int x = bx + lx, y = by + ly;
    int pidx = b * HW + y * Wd + x;
    g_fw[br][pidx] = __expf(-tt * tt);

    g_acc4[br][pidx] = make_float4(0.f, 0.f, 0.f, 0.f);
    reinterpret_cast<float*>(g_accR4[br])[pidx] = 0.f;
}

// ---------------------------------------------------------------------------
// Forward gaussian splat, hybrid accumulation:
//  - colors+pw: 16 red.v4 per pixel at L2 (irreducible 16B payloads)
//  - rw: shared-memory tile (48x24, halo 8) + cp.reduce.async.bulk row flush;
//    taps outside the window (|flow| >= 7, ~never for N(0,1)) fall back to a
//    direct global atomicAdd for correctness on arbitrary flow.
// TAO_R truncation is dead (min tap weight exp(-8/4.5)=0.169 > 0.05).
// ---------------------------------------------------------------------------
__global__ void __launch_bounds__(TX * TY) k_splat(
    const float* __restrict__ img, const float* __restrict__ flow, int br)
{
    __shared__ __align__(16) float srw[SWH][SWW];

    int b  = blockIdx.z;
    int bx = blockIdx.x * TX;
    int by = blockIdx.y * TY;
    int lx = threadIdx.x, ly = threadIdx.y;
    int t  = ly * TX + lx;
    int x  = bx + lx, y = by + ly;
    int r  = y * Wd + x;
    int p  = b * HW + r;

    // zero smem tile
    {
        float4* sz = reinterpret_cast<float4*>(&srw[0][0]);
#pragma unroll
        for (int i = t; i < SWH * SWW / 4; i += TX * TY)
            sz[i] = make_float4(0.f, 0.f, 0.f, 0.f);
    }
    __syncthreads();

    {
        float u = __ldg(flow + b * 2 * HW + r);
        float v = __ldg(flow + b * 2 * HW + HW + r);
        float f = g_fw[br][p];

        const float* imb = img + b * 3 * HW + r;
        float s0 = __ldg(imb) * f;
        float s1 = __ldg(imb + HW) * f;
        float s2 = __ldg(imb + 2 * HW) * f;

        float tx = (float)x + u, ty = (float)y + v;
        float fx = floorf(tx), fy = floorf(ty);
        int ix0 = (int)fx - 1, iy0 = (int)fy - 1;

        float gxv[4], gyv[4];
#pragma unroll
        for (int k = 0; k < 4; k++) {
            float dx = tx - (fx + (float)(k - 1));
            float dy = ty - (fy + (float)(k - 1));
            gxv[k] = __expf(-dx * dx * INV2S2);
            gyv[k] = __expf(-dy * dy * INV2S2);
        }

        float4* acc  = g_acc4[br];
        float*  accR = reinterpret_cast<float*>(g_accR4[br]);
        int xw0 = bx - HLO, yw0 = by - HLO;

#pragma unroll
        for (int j = 0; j < 4; j++) {
            int iy = iy0 + j;
            if ((unsigned)iy >= (unsigned)Hd) continue;
            int rowb = b * HW + iy * Wd;
            float gy = gyv[j];
            int sy = iy - yw0;
#pragma unroll
            for (int i = 0; i < 4; i++) {
                int ix = ix0 + i;
                if ((unsigned)ix >= (unsigned)Wd) continue;
                float w = gxv[i] * gy;
                asm volatile("red.global.add.v4.f32 [%0], {%1, %2, %3, %4};"
                             :: "l"(acc + rowb + ix), "f"(s0 * w), "f"(s1 * w),
                                "f"(s2 * w), "f"(f * w)
                             : "memory");
                int sx = ix - xw0;
                if ((unsigned)sx < (unsigned)SWW && (unsigned)sy < (unsigned)SWH)
                    atomicAdd(&srw[sy][sx], w);
                else
                    atomicAdd(accR + rowb + ix, w);   // ~never taken for N(0,1) flow
            }
        }
    }
    __syncthreads();

    // flush rw tile: one bulk async reduce per valid row (threads 0..SWH-1)
    if (t < SWH) {
        int yy = by - HLO + t;
        if ((unsigned)yy < (unsigned)Hd) {
            int xs = max(bx - HLO, 0);
            int xe = min(bx + TX + HLO, Wd);
            int nbytes = (xe - xs) * 4;                 // multiple of 16 (bounds are mult. of 8)
            float* dst = reinterpret_cast<float*>(g_accR4[br]) + b * HW + yy * Wd + xs;
            uint32_t saddr = (uint32_t)__cvta_generic_to_shared(&srw[t][xs - (bx - HLO)]);
            asm volatile("fence.proxy.async.shared::cta;" ::: "memory");
            asm volatile("cp.reduce.async.bulk.global.shared::cta.bulk_group.add.f32 "
                         "[%0], [%1], %2;"
                         :: "l"(dst), "r"(saddr), "r"(nbytes) : "memory");
            asm volatile("cp.async.bulk.commit_group;" ::: "memory");
            asm volatile("cp.async.bulk.wait_group 0;" ::: "memory");
        }
    }
}

// ---------------------------------------------------------------------------
// Final adaptive blend — 4 px/thread, fully vectorized accesses.
// ---------------------------------------------------------------------------
__global__ void __launch_bounds__(256) k_blend(float* __restrict__ out) {
    int q = blockIdx.x * 256 + threadIdx.x;   // group of 4 pixels
    if (q >= BHW / 4) return;
    int p0 = q * 4;
    int b  = p0 / HW;
    int r  = p0 - b * HW;

    float4 R1v = g_accR4[0][q];
    float4 R2v = g_accR4[1][q];
    const float* R1p = &R1v.x;
    const float* R2p = &R2v.x;

    float4 o0, o1, o2;
    float* o0p = &o0.x; float* o1p = &o1.x; float* o2p = &o2.x;

#pragma unroll
    for (int k = 0; k < 4; k++) {
        float4 A = g_acc4[0][p0 + k];
        float4 C = g_acc4[1][p0 + k];
        float w1 = A.w / (R1p[k] + THRESH_);
        float w2 = C.w / (R2p[k] + THRESH_);
        float q1 = w1 / (A.w + THRESH_);
        float q2 = w2 / (C.w + THRESH_);
        float dn = 1.f / (w1 + w2 + EPS_);
        o0p[k] = (A.x * q1 + C.x * q2) * dn;
        o1p[k] = (A.y * q1 + C.y * q2) * dn;
        o2p[k] = (A.z * q1 + C.z * q2) * dn;
    }

    float* ob = out + b * 3 * HW + r;
    *reinterpret_cast<float4*>(ob)          = o0;
    *reinterpret_cast<float4*>(ob + HW)     = o1;
    *reinterpret_cast<float4*>(ob + 2 * HW) = o2;
}

// ---------------------------------------------------------------------------
extern "C" void kernel_launch(void* const* d_in, const int* in_sizes, int n_in,
                              void* d_out, int out_size)
{
    const float* i1 = (const float*)d_in[0];
    const float* i2 = (const float*)d_in[1];
    const float* f1 = (const float*)d_in[2];
    const float* f2 = (const float*)d_in[3];
    float* out = (float*)d_out;

    dim3 ge(Wd / EX, Hd / EY, Bd * 2);
    dim3 be(EX, EY, 1);
    dim3 gs(Wd / TX, Hd / TY, Bd);
    dim3 bs(TX, TY, 1);
    int nb = (BHW / 4 + 255) / 256;

    k_errfw<<<ge, be>>>(i1, i2, f1, f2);   // launch 1 (both branches, zeros acc)
    k_splat<<<gs, bs>>>(i1, f1, 0);        // launch 2
    k_splat<<<gs, bs>>>(i2, f2, 1);        // launch 3
    k_blend<<<nb, 256>>>(out);             // launch 4
    // second graph iteration: launches 5..8 -> -s 5 capture lands on a splat
}

// round 6
// speedup vs baseline: 1.0482x; 1.0482x over previous
#include <cuda_runtime.h>
#include <cstdint>

// Problem shape (fixed): input1/2 [4,3,720,1280] f32, flow3/4 [4,2,720,1280] f32
namespace {
constexpr int Wd  = 1280;
constexpr int Hd  = 720;
constexpr int Bd  = 4;
constexpr int HW  = Hd * Wd;
constexpr int BHW = Bd * HW;

constexpr float INV_LE  = 255.0f / 30.0f;              // 1 / LAMBDA_E
constexpr float INV2S2  = 1.0f / (2.0f * 1.5f * 1.5f); // 1/(2*sigma_d^2)
constexpr float THRESH_ = 1e-6f;
constexpr float EPS_    = 1e-6f;

constexpr int EX = 32, EY = 8;    // errfw tile (256 threads) — round-4 config
constexpr int TX = 32, TY = 16;   // splat tile (512 threads)
constexpr int HLO = 8;            // splat smem halo (covers |flow| < 7)
constexpr int SWW = TX + 2 * HLO; // 48
constexpr int SWH = TY + 2 * HLO; // 32
}

// Scratch: branch-indexed. acc4 = (p_r, p_g, p_b, pw), accR = rw.
__device__ float  g_fw   [2][BHW];
__device__ float4 g_acc4 [2][BHW];
__device__ float4 g_accR4[2][BHW / 4];

// ---------------------------------------------------------------------------
// Fused: photometric error (bilinear warp) + 3x3 box + fw = exp(-(e/le)^2),
// plus zeroing of this pixel's splat accumulators. grid.z = b + 4*br.
// ---------------------------------------------------------------------------
__device__ __forceinline__ float photo_err(
    const float* __restrict__ i1, const float* __restrict__ i2,
    const float* __restrict__ flow, int b, int x, int y)
{
    int r = y * Wd + x;
    float u = __ldg(flow + b * 2 * HW + r);
    float v = __ldg(flow + b * 2 * HW + HW + r);

    float gx = fminf(fmaxf((float)x + u, 0.f), (float)(Wd - 1));
    float gy = fminf(fmaxf((float)y + v, 0.f), (float)(Hd - 1));
    float x0f = floorf(gx), y0f = floorf(gy);
    int x0 = (int)x0f, y0 = (int)y0f;
    int x1 = min(x0 + 1, Wd - 1), y1 = min(y0 + 1, Hd - 1);
    float wx = gx - x0f, wy = gy - y0f;
    float w00 = (1.f - wx) * (1.f - wy);
    float w01 = wx * (1.f - wy);
    float w10 = (1.f - wx) * wy;
    float w11 = wx * wy;

    const float* i2b = i2 + b * 3 * HW;
    const float* i1b = i1 + b * 3 * HW;
    float e = 0.f;
#pragma unroll
    for (int c = 0; c < 3; c++) {
        const float* ip = i2b + c * HW;
        float wv = __ldg(ip + y0 * Wd + x0) * w00 + __ldg(ip + y0 * Wd + x1) * w01
                 + __ldg(ip + y1 * Wd + x0) * w10 + __ldg(ip + y1 * Wd + x1) * w11;
        e += fabsf(__ldg(i1b + c * HW + r) - wv);
    }
    return e * (1.f / 3.f);
}

__global__ void __launch_bounds__(EX * EY) k_errfw(
    const float* __restrict__ in1, const float* __restrict__ in2,
    const float* __restrict__ fl1, const float* __restrict__ fl2)
{
    __shared__ float serr[EY + 2][EX + 2];

    int br = blockIdx.z >> 2;
    int b  = blockIdx.z & 3;
    const float* i1   = br ? in2 : in1;
    const float* i2   = br ? in1 : in2;
    const float* flow = br ? fl2 : fl1;

    int bx = blockIdx.x * EX;
    int by = blockIdx.y * EY;
    int t  = threadIdx.y * EX + threadIdx.x;

    for (int idx = t; idx < (EY + 2) * (EX + 2); idx += EX * EY) {
        int j = idx / (EX + 2);
        int i = idx - j * (EX + 2);
        int ex = bx + i - 1;
        int ey = by + j - 1;
        float e = 0.f;
        if ((unsigned)ex < (unsigned)Wd && (unsigned)ey < (unsigned)Hd)
            e = photo_err(i1, i2, flow, b, ex, ey);
        serr[j][i] = e;
    }
    __syncthreads();

    int lx = threadIdx.x, ly = threadIdx.y;
    float s = 0.f;
#pragma unroll
    for (int j = 0; j < 3; j++)
#pragma unroll
        for (int i = 0; i < 3; i++)
            s += serr[ly + j][lx + i];

    float tt = s * (1.f / 9.f) * INV_LE;
    int x = bx + lx, y = by + ly;
    int pidx = b * HW + y * Wd + x;
    g_fw[br][pidx] = __expf(-tt * tt);

    g_acc4[br][pidx] = make_float4(0.f, 0.f, 0.f, 0.f);
    reinterpret_cast<float*>(g_accR4[br])[pidx] = 0.f;
}

// ---------------------------------------------------------------------------
// Forward gaussian splat (both branches in ONE launch, grid.z = b + 4*br):
//  - colors+pw: 16 red.v4 per pixel at L2 (irreducible 16B payloads)
//  - rw: shared-memory tile (48x32, halo 8) + cp.reduce.async.bulk row flush;
//    taps outside the window (|flow| >= 7, ~never for N(0,1)) fall back to a
//    direct global atomicAdd for correctness on arbitrary flow.
// TAO_R truncation is dead (min tap weight exp(-8/4.5)=0.169 > 0.05).
// ---------------------------------------------------------------------------
__global__ void __launch_bounds__(TX * TY) k_splat(
    const float* __restrict__ in1, const float* __restrict__ in2,
    const float* __restrict__ fl1, const float* __restrict__ fl2)
{
    __shared__ __align__(16) float srw[SWH][SWW];

    int br = blockIdx.z >> 2;
    int b  = blockIdx.z & 3;
    const float* img  = br ? in2 : in1;
    const float* flow = br ? fl2 : fl1;

    int bx = blockIdx.x * TX;
    int by = blockIdx.y * TY;
    int lx = threadIdx.x, ly = threadIdx.y;
    int t  = ly * TX + lx;
    int x  = bx + lx, y = by + ly;
    int r  = y * Wd + x;
    int p  = b * HW + r;

    // zero smem tile
    {
        float4* sz = reinterpret_cast<float4*>(&srw[0][0]);
#pragma unroll
        for (int i = t; i < SWH * SWW / 4; i += TX * TY)
            sz[i] = make_float4(0.f, 0.f, 0.f, 0.f);
    }
    __syncthreads();

    {
        float u = __ldg(flow + b * 2 * HW + r);
        float v = __ldg(flow + b * 2 * HW + HW + r);
        float f = g_fw[br][p];

        const float* imb = img + b * 3 * HW + r;
        float s0 = __ldg(imb) * f;
        float s1 = __ldg(imb + HW) * f;
        float s2 = __ldg(imb + 2 * HW) * f;

        float tx = (float)x + u, ty = (float)y + v;
        float fx = floorf(tx), fy = floorf(ty);
        int ix0 = (int)fx - 1, iy0 = (int)fy - 1;

        float gxv[4], gyv[4];
#pragma unroll
        for (int k = 0; k < 4; k++) {
            float dx = tx - (fx + (float)(k - 1));
            float dy = ty - (fy + (float)(k - 1));
            gxv[k] = __expf(-dx * dx * INV2S2);
            gyv[k] = __expf(-dy * dy * INV2S2);
        }

        float4* acc  = g_acc4[br];
        float*  accR = reinterpret_cast<float*>(g_accR4[br]);
        int xw0 = bx - HLO, yw0 = by - HLO;

#pragma unroll
        for (int j = 0; j < 4; j++) {
            int iy = iy0 + j;
            if ((unsigned)iy >= (unsigned)Hd) continue;
            int rowb = b * HW + iy * Wd;
            float gy = gyv[j];
            int sy = iy - yw0;
#pragma unroll
            for (int i = 0; i < 4; i++) {
                int ix = ix0 + i;
                if ((unsigned)ix >= (unsigned)Wd) continue;
                float w = gxv[i] * gy;
                asm volatile("red.global.add.v4.f32 [%0], {%1, %2, %3, %4};"
                             :: "l"(acc + rowb + ix), "f"(s0 * w), "f"(s1 * w),
                                "f"(s2 * w), "f"(f * w)
                             : "memory");
                int sx = ix - xw0;
                if ((unsigned)sx < (unsigned)SWW && (unsigned)sy < (unsigned)SWH)
                    atomicAdd(&srw[sy][sx], w);
                else
                    atomicAdd(accR + rowb + ix, w);   // ~never taken for N(0,1) flow
            }
        }
    }
    __syncthreads();

    // flush rw tile: one bulk async reduce per valid row (threads 0..SWH-1)
    if (t < SWH) {
        int yy = by - HLO + t;
        if ((unsigned)yy < (unsigned)Hd) {
            int xs = max(bx - HLO, 0);
            int xe = min(bx + TX + HLO, Wd);
            int nbytes = (xe - xs) * 4;                 // multiple of 16 (bounds are mult. of 8)
            float* dst = reinterpret_cast<float*>(g_accR4[br]) + b * HW + yy * Wd + xs;
            uint32_t saddr = (uint32_t)__cvta_generic_to_shared(&srw[t][xs - (bx - HLO)]);
            asm volatile("fence.proxy.async.shared::cta;" ::: "memory");
            asm volatile("cp.reduce.async.bulk.global.shared::cta.bulk_group.add.f32 "
                         "[%0], [%1], %2;"
                         :: "l"(dst), "r"(saddr), "r"(nbytes) : "memory");
            asm volatile("cp.async.bulk.commit_group;" ::: "memory");
            asm volatile("cp.async.bulk.wait_group 0;" ::: "memory");
        }
    }
}

// ---------------------------------------------------------------------------
// Final adaptive blend — 4 px/thread, fully vectorized accesses.
// ---------------------------------------------------------------------------
__global__ void __launch_bounds__(256) k_blend(float* __restrict__ out) {
    int q = blockIdx.x * 256 + threadIdx.x;   // group of 4 pixels
    if (q >= BHW / 4) return;
    int p0 = q * 4;
    int b  = p0 / HW;
    int r  = p0 - b * HW;

    float4 R1v = g_accR4[0][q];
    float4 R2v = g_accR4[1][q];
    const float* R1p = &R1v.x;
    const float* R2p = &R2v.x;

    float4 o0, o1, o2;
    float* o0p = &o0.x; float* o1p = &o1.x; float* o2p = &o2.x;

#pragma unroll
    for (int k = 0; k < 4; k++) {
        float4 A = g_acc4[0][p0 + k];
        float4 C = g_acc4[1][p0 + k];
        float w1 = A.w / (R1p[k] + THRESH_);
        float w2 = C.w / (R2p[k] + THRESH_);
        float q1 = w1 / (A.w + THRESH_);
        float q2 = w2 / (C.w + THRESH_);
        float dn = 1.f / (w1 + w2 + EPS_);
        o0p[k] = (A.x * q1 + C.x * q2) * dn;
        o1p[k] = (A.y * q1 + C.y * q2) * dn;
        o2p[k] = (A.z * q1 + C.z * q2) * dn;
    }

    float* ob = out + b * 3 * HW + r;
    *reinterpret_cast<float4*>(ob)          = o0;
    *reinterpret_cast<float4*>(ob + HW)     = o1;
    *reinterpret_cast<float4*>(ob + 2 * HW) = o2;
}

// ---------------------------------------------------------------------------
extern "C" void kernel_launch(void* const* d_in, const int* in_sizes, int n_in,
                              void* d_out, int out_size)
{
    const float* i1 = (const float*)d_in[0];
    const float* i2 = (const float*)d_in[1];
    const float* f1 = (const float*)d_in[2];
    const float* f2 = (const float*)d_in[3];
    float* out = (float*)d_out;

    dim3 ge(Wd / EX, Hd / EY, Bd * 2);
    dim3 be(EX, EY, 1);
    dim3 gs(Wd / TX, Hd / TY, Bd * 2);
    dim3 bs(TX, TY, 1);
    int nb = (BHW / 4 + 255) / 256;

    k_errfw<<<ge, be>>>(i1, i2, f1, f2);   // launch 1 (both branches, zeros acc)
    k_splat<<<gs, bs>>>(i1, i2, f1, f2);   // launch 2 (both branches, merged)
    k_blend<<<nb, 256>>>(out);             // launch 3
}

// round 7
// speedup vs baseline: 1.0655x; 1.0164x over previous
#include <cuda_runtime.h>
#include <cstdint>

// Problem shape (fixed): input1/2 [4,3,720,1280] f32, flow3/4 [4,2,720,1280] f32
namespace {
constexpr int Wd  = 1280;
constexpr int Hd  = 720;
constexpr int Bd  = 4;
constexpr int HW  = Hd * Wd;
constexpr int BHW = Bd * HW;

constexpr float INV_LE  = 255.0f / 30.0f;              // 1 / LAMBDA_E
constexpr float INV2S2  = 1.0f / (2.0f * 1.5f * 1.5f); // 1/(2*sigma_d^2)
constexpr float THRESH_ = 1e-6f;
constexpr float EPS_    = 1e-6f;

constexpr int EX = 32, EY = 8;    // errfw tile (256 threads)
constexpr int TX = 32, TY = 8;    // splat tile (256 threads) — round-4 config
constexpr int HLO = 8;            // splat smem halo (covers |flow| < 7)
constexpr int SWW = TX + 2 * HLO; // 48
constexpr int SWH = TY + 2 * HLO; // 24
}

// Scratch: branch-indexed. acc4 = (p_r, p_g, p_b, pw), accR = rw.
__device__ float  g_fw   [2][BHW];
__device__ float4 g_acc4 [2][BHW];
__device__ float4 g_accR4[2][BHW / 4];

// ---------------------------------------------------------------------------
// Fused: photometric error (bilinear warp) + 3x3 box + fw = exp(-(e/le)^2),
// plus zeroing of this pixel's splat accumulators. grid.z = b + 4*br.
// ---------------------------------------------------------------------------
__device__ __forceinline__ float photo_err(
    const float* __restrict__ i1, const float* __restrict__ i2,
    const float* __restrict__ flow, int b, int x, int y)
{
    int r = y * Wd + x;
    float u = __ldg(flow + b * 2 * HW + r);
    float v = __ldg(flow + b * 2 * HW + HW + r);

    float gx = fminf(fmaxf((float)x + u, 0.f), (float)(Wd - 1));
    float gy = fminf(fmaxf((float)y + v, 0.f), (float)(Hd - 1));
    float x0f = floorf(gx), y0f = floorf(gy);
    int x0 = (int)x0f, y0 = (int)y0f;
    int x1 = min(x0 + 1, Wd - 1), y1 = min(y0 + 1, Hd - 1);
    float wx = gx - x0f, wy = gy - y0f;
    float w00 = (1.f - wx) * (1.f - wy);
    float w01 = wx * (1.f - wy);
    float w10 = (1.f - wx) * wy;
    float w11 = wx * wy;

    const float* i2b = i2 + b * 3 * HW;
    const float* i1b = i1 + b * 3 * HW;
    float e = 0.f;
#pragma unroll
    for (int c = 0; c < 3; c++) {
        const float* ip = i2b + c * HW;
        float wv = __ldg(ip + y0 * Wd + x0) * w00 + __ldg(ip + y0 * Wd + x1) * w01
                 + __ldg(ip + y1 * Wd + x0) * w10 + __ldg(ip + y1 * Wd + x1) * w11;
        e += fabsf(__ldg(i1b + c * HW + r) - wv);
    }
    return e * (1.f / 3.f);
}

__global__ void __launch_bounds__(EX * EY) k_errfw(
    const float* __restrict__ in1, const float* __restrict__ in2,
    const float* __restrict__ fl1, const float* __restrict__ fl2)
{
    __shared__ float serr[EY + 2][EX + 2];

    int br = blockIdx.z >> 2;
    int b  = blockIdx.z & 3;
    const float* i1   = br ? in2 : in1;
    const float* i2   = br ? in1 : in2;
    const float* flow = br ? fl2 : fl1;

    int bx = blockIdx.x * EX;
    int by = blockIdx.y * EY;
    int t  = threadIdx.y * EX + threadIdx.x;

    for (int idx = t; idx < (EY + 2) * (EX + 2); idx += EX * EY) {
        int j = idx / (EX + 2);
        int i = idx - j * (EX + 2);
        int ex = bx + i - 1;
        int ey = by + j - 1;
        float e = 0.f;
        if ((unsigned)ex < (unsigned)Wd && (unsigned)ey < (unsigned)Hd)
            e = photo_err(i1, i2, flow, b, ex, ey);
        serr[j][i] = e;
    }
    __syncthreads();

    int lx = threadIdx.x, ly = threadIdx.y;
    float s = 0.f;
#pragma unroll
    for (int j = 0; j < 3; j++)
#pragma unroll
        for (int i = 0; i < 3; i++)
            s += serr[ly + j][lx + i];

    float tt = s * (1.f / 9.f) * INV_LE;
    int x = bx + lx, y = by + ly;
    int pidx = b * HW + y * Wd + x;
    g_fw[br][pidx] = __expf(-tt * tt);

    g_acc4[br][pidx] = make_float4(0.f, 0.f, 0.f, 0.f);
    reinterpret_cast<float*>(g_accR4[br])[pidx] = 0.f;
}

// ---------------------------------------------------------------------------
// Forward gaussian splat (both branches in ONE launch, grid.z = b + 4*br):
//  - colors+pw: 16 red.v4 per pixel at L2 (irreducible 16B payloads)
//  - rw: shared-memory tile (48x24, halo 8) + cp.reduce.async.bulk row flush;
//    taps outside the window (|flow| >= 7, ~never for N(0,1)) fall back to a
//    direct global atomicAdd for correctness on arbitrary flow.
// TAO_R truncation is dead (min tap weight exp(-8/4.5)=0.169 > 0.05).
// ---------------------------------------------------------------------------
__global__ void __launch_bounds__(TX * TY) k_splat(
    const float* __restrict__ in1, const float* __restrict__ in2,
    const float* __restrict__ fl1, const float* __restrict__ fl2)
{
    __shared__ __align__(16) float srw[SWH][SWW];

    int br = blockIdx.z >> 2;
    int b  = blockIdx.z & 3;
    const float* img  = br ? in2 : in1;
    const float* flow = br ? fl2 : fl1;

    int bx = blockIdx.x * TX;
    int by = blockIdx.y * TY;
    int lx = threadIdx.x, ly = threadIdx.y;
    int t  = ly * TX + lx;
    int x  = bx + lx, y = by + ly;
    int r  = y * Wd + x;
    int p  = b * HW + r;

    // zero smem tile
    {
        float4* sz = reinterpret_cast<float4*>(&srw[0][0]);
#pragma unroll
        for (int i = t; i < SWH * SWW / 4; i += TX * TY)
            sz[i] = make_float4(0.f, 0.f, 0.f, 0.f);
    }
    __syncthreads();

    {
        float u = __ldg(flow + b * 2 * HW + r);
        float v = __ldg(flow + b * 2 * HW + HW + r);
        float f = g_fw[br][p];

        const float* imb = img + b * 3 * HW + r;
        float s0 = __ldg(imb) * f;
        float s1 = __ldg(imb + HW) * f;
        float s2 = __ldg(imb + 2 * HW) * f;

        float tx = (float)x + u, ty = (float)y + v;
        float fx = floorf(tx), fy = floorf(ty);
        int ix0 = (int)fx - 1, iy0 = (int)fy - 1;

        float gxv[4], gyv[4];
#pragma unroll
        for (int k = 0; k < 4; k++) {
            float dx = tx - (fx + (float)(k - 1));
            float dy = ty - (fy + (float)(k - 1));
            gxv[k] = __expf(-dx * dx * INV2S2);
            gyv[k] = __expf(-dy * dy * INV2S2);
        }

        float4* acc  = g_acc4[br];
        float*  accR = reinterpret_cast<float*>(g_accR4[br]);
        int xw0 = bx - HLO, yw0 = by - HLO;

#pragma unroll
        for (int j = 0; j < 4; j++) {
            int iy = iy0 + j;
            if ((unsigned)iy >= (unsigned)Hd) continue;
            int rowb = b * HW + iy * Wd;
            float gy = gyv[j];
            int sy = iy - yw0;
#pragma unroll
            for (int i = 0; i < 4; i++) {
                int ix = ix0 + i;
                if ((unsigned)ix >= (unsigned)Wd) continue;
                float w = gxv[i] * gy;
                asm volatile("red.global.add.v4.f32 [%0], {%1, %2, %3, %4};"
                             :: "l"(acc + rowb + ix), "f"(s0 * w), "f"(s1 * w),
                                "f"(s2 * w), "f"(f * w)
                             : "memory");
                int sx = ix - xw0;
                if ((unsigned)sx < (unsigned)SWW && (unsigned)sy < (unsigned)SWH)
                    atomicAdd(&srw[sy][sx], w);
                else
                    atomicAdd(accR + rowb + ix, w);   // ~never taken for N(0,1) flow
            }
        }
    }
    __syncthreads();

    // flush rw tile: one bulk async reduce per valid row (threads 0..SWH-1)
    if (t < SWH) {
        int yy = by - HLO + t;
        if ((unsigned)yy < (unsigned)Hd) {
            int xs = max(bx - HLO, 0);
            int xe = min(bx + TX + HLO, Wd);
            int nbytes = (xe - xs) * 4;                 // multiple of 16 (bounds are mult. of 8)
            float* dst = reinterpret_cast<float*>(g_accR4[br]) + b * HW + yy * Wd + xs;
            uint32_t saddr = (uint32_t)__cvta_generic_to_shared(&srw[t][xs - (bx - HLO)]);
            asm volatile("fence.proxy.async.shared::cta;" ::: "memory");
            asm volatile("cp.reduce.async.bulk.global.shared::cta.bulk_group.add.f32 "
                         "[%0], [%1], %2;"
                         :: "l"(dst), "r"(saddr), "r"(nbytes) : "memory");
            asm volatile("cp.async.bulk.commit_group;" ::: "memory");
            asm volatile("cp.async.bulk.wait_group 0;" ::: "memory");
        }
    }
}

// ---------------------------------------------------------------------------
// Final adaptive blend — 4 px/thread, fully vectorized accesses.
// ---------------------------------------------------------------------------
__global__ void __launch_bounds__(256) k_blend(float* __restrict__ out) {
    int q = blockIdx.x * 256 + threadIdx.x;   // group of 4 pixels
    if (q >= BHW / 4) return;
    int p0 = q * 4;
    int b  = p0 / HW;
    int r  = p0 - b * HW;

    float4 R1v = g_accR4[0][q];
    float4 R2v = g_accR4[1][q];
    const float* R1p = &R1v.x;
    const float* R2p = &R2v.x;

    float4 o0, o1, o2;
    float* o0p = &o0.x; float* o1p = &o1.x; float* o2p = &o2.x;

#pragma unroll
    for (int k = 0; k < 4; k++) {
        float4 A = g_acc4[0][p0 + k];
        float4 C = g_acc4[1][p0 + k];
        float w1 = A.w / (R1p[k] + THRESH_);
        float w2 = C.w / (R2p[k] + THRESH_);
        float q1 = w1 / (A.w + THRESH_);
        float q2 = w2 / (C.w + THRESH_);
        float dn = 1.f / (w1 + w2 + EPS_);
        o0p[k] = (A.x * q1 + C.x * q2) * dn;
        o1p[k] = (A.y * q1 + C.y * q2) * dn;
        o2p[k] = (A.z * q1 + C.z * q2) * dn;
    }

    float* ob = out + b * 3 * HW + r;
    *reinterpret_cast<float4*>(ob)          = o0;
    *reinterpret_cast<float4*>(ob + HW)     = o1;
    *reinterpret_cast<float4*>(ob + 2 * HW) = o2;
}

// ---------------------------------------------------------------------------
extern "C" void kernel_launch(void* const* d_in, const int* in_sizes, int n_in,
                              void* d_out, int out_size)
{
    const float* i1 = (const float*)d_in[0];
    const float* i2 = (const float*)d_in[1];
    const float* f1 = (const float*)d_in[2];
    const float* f2 = (const float*)d_in[3];
    float* out = (float*)d_out;

    dim3 ge(Wd / EX, Hd / EY, Bd * 2);
    dim3 be(EX, EY, 1);
    dim3 gs(Wd / TX, Hd / TY, Bd * 2);
    dim3 bs(TX, TY, 1);
    int nb = (BHW / 4 + 255) / 256;

    k_errfw<<<ge, be>>>(i1, i2, f1, f2);   // launch 1 (both branches, zeros acc)
    k_splat<<<gs, bs>>>(i1, i2, f1, f2);   // launch 2 (both branches, merged)
    k_blend<<<nb, 256>>>(out);             // launch 3
}